// round 1
// baseline (speedup 1.0000x reference)
#include <cuda_runtime.h>
#include <cstdint>

#define BG   64
#define NN   384
#define NOISE_D 128
#define CED_D   64
#define HID_D   512
#define FEAT_D  256
#define IN_D    192           // NOISE + CED
#define M_ROWS  (BG*NN)       // 24576
#define P_PAIR  73536         // N*(N-1)/2
#define K_SEL   3677          // round(0.05 * P)

// output layout (float32, concatenated reference tuple)
#define X_SIZE   (M_ROWS*FEAT_D)        // 6291456
#define E0       X_SIZE
#define ROWLEN   (BG*2*K_SEL)           // 470656
#define BB       (E0 + 2*ROWLEN)        // 7232768
#define TPB      (BB + M_ROWS)          // 7257344

// ---------------- scratch (device globals; no allocation) ----------------
__device__ float g_inp[M_ROWS*IN_D];
__device__ float g_y1[M_ROWS*HID_D];
__device__ float g_h[M_ROWS*HID_D];
__device__ float g_sq[M_ROWS];
__device__ float g_probs[BG*P_PAIR];

// ---------------- build concatenated input ----------------
__global__ void build_inp_kernel(const float* __restrict__ z,
                                 const int* __restrict__ labels,
                                 const float* __restrict__ emb) {
    int node = blockIdx.x;
    int t = threadIdx.x;   // 192
    int b = node / NN;
    float v;
    if (t < NOISE_D) v = z[node*NOISE_D + t];
    else             v = emb[labels[b]*CED_D + (t - NOISE_D)];
    g_inp[node*IN_D + t] = v;
}

// ---------------- tiled fp32 GEMM: C = act(A@B + bias) ----------------
// A [M,K] rm, B [K,Nc] rm, C [M,Nc] rm. M%64==0, Nc%64==0, K%16==0.
template<bool RELU>
__global__ void gemm_bias_kernel(const float* __restrict__ A,
                                 const float* __restrict__ Bw,
                                 const float* __restrict__ bias,
                                 float* __restrict__ C,
                                 int M, int Kd, int Nc) {
    __shared__ float As[16][65];
    __shared__ float Bs[16][65];
    int tid = threadIdx.x;            // 256
    int m0 = blockIdx.y * 64, n0 = blockIdx.x * 64;
    int tx = tid & 15, ty = tid >> 4;
    float acc[4][4];
#pragma unroll
    for (int i = 0; i < 4; i++)
#pragma unroll
        for (int j = 0; j < 4; j++) acc[i][j] = 0.f;

    int ar = tid >> 2;          // 0..63
    int ac = (tid & 3) * 4;     // 0,4,8,12
    int br = tid >> 4;          // 0..15
    int bc = (tid & 15) * 4;    // 0..60

    for (int k0 = 0; k0 < Kd; k0 += 16) {
        float4 av = *(const float4*)(A + (size_t)(m0 + ar)*Kd + k0 + ac);
        As[ac+0][ar] = av.x; As[ac+1][ar] = av.y;
        As[ac+2][ar] = av.z; As[ac+3][ar] = av.w;
        float4 bv = *(const float4*)(Bw + (size_t)(k0 + br)*Nc + n0 + bc);
        Bs[br][bc+0] = bv.x; Bs[br][bc+1] = bv.y;
        Bs[br][bc+2] = bv.z; Bs[br][bc+3] = bv.w;
        __syncthreads();
#pragma unroll
        for (int k = 0; k < 16; k++) {
            float a[4], bb[4];
#pragma unroll
            for (int u = 0; u < 4; u++) a[u]  = As[k][ty*4+u];
#pragma unroll
            for (int u = 0; u < 4; u++) bb[u] = Bs[k][tx*4+u];
#pragma unroll
            for (int i = 0; i < 4; i++)
#pragma unroll
                for (int j = 0; j < 4; j++) acc[i][j] += a[i]*bb[j];
        }
        __syncthreads();
    }
#pragma unroll
    for (int i = 0; i < 4; i++) {
        int m = m0 + ty*4 + i;
#pragma unroll
        for (int j = 0; j < 4; j++) {
            int n = n0 + tx*4 + j;
            float v = acc[i][j] + bias[n];
            if (RELU) v = fmaxf(v, 0.f);
            C[(size_t)m*Nc + n] = v;
        }
    }
}

// ---------------- row sum of squares of h ----------------
__global__ void sq_kernel() {
    int row = blockIdx.x * 8 + (threadIdx.x >> 5);
    int lane = threadIdx.x & 31;
    const float* hp = g_h + (size_t)row * HID_D;
    float s = 0.f;
    for (int k = lane; k < HID_D; k += 32) { float v = hp[k]; s += v*v; }
#pragma unroll
    for (int o = 16; o > 0; o >>= 1) s += __shfl_down_sync(0xFFFFFFFFu, s, o);
    if (lane == 0) g_sq[row] = s;
}

// ---------------- gram -> dist -> sigmoid probs (upper-tri pairs) ----------------
__global__ void gram_probs_kernel(const float* __restrict__ thr_p) {
    // blockIdx.x in [0,21): tile pair (ti,tj), ti<=tj over 6 tiles of 64
    int q = blockIdx.x, ti = 0, rem = q;
    for (;;) { int cnt = 6 - ti; if (rem < cnt) break; rem -= cnt; ti++; }
    int tj = ti + rem;
    int b = blockIdx.y;
    int gbase = b * NN;
    float thr = *thr_p;

    __shared__ float As[16][65];   // [k][i-node]
    __shared__ float Bs[16][65];   // [k][j-node]
    int tid = threadIdx.x;         // 256
    int tx = tid & 15, ty = tid >> 4;
    float acc[4][4];
#pragma unroll
    for (int i = 0; i < 4; i++)
#pragma unroll
        for (int j = 0; j < 4; j++) acc[i][j] = 0.f;

    int r = tid >> 2;              // 0..63
    int c4 = (tid & 3) * 4;        // 0,4,8,12
    const float* Ha = g_h + (size_t)(gbase + ti*64 + r) * HID_D + c4;
    const float* Hb = g_h + (size_t)(gbase + tj*64 + r) * HID_D + c4;

    for (int k0 = 0; k0 < HID_D; k0 += 16) {
        float4 av = *(const float4*)(Ha + k0);
        As[c4+0][r] = av.x; As[c4+1][r] = av.y; As[c4+2][r] = av.z; As[c4+3][r] = av.w;
        float4 bv = *(const float4*)(Hb + k0);
        Bs[c4+0][r] = bv.x; Bs[c4+1][r] = bv.y; Bs[c4+2][r] = bv.z; Bs[c4+3][r] = bv.w;
        __syncthreads();
#pragma unroll
        for (int k = 0; k < 16; k++) {
            float a[4], bb[4];
#pragma unroll
            for (int u = 0; u < 4; u++) a[u]  = As[k][ty*4+u];
#pragma unroll
            for (int u = 0; u < 4; u++) bb[u] = Bs[k][tx*4+u];
#pragma unroll
            for (int i = 0; i < 4; i++)
#pragma unroll
                for (int j = 0; j < 4; j++) acc[i][j] += a[i]*bb[j];
        }
        __syncthreads();
    }
#pragma unroll
    for (int i = 0; i < 4; i++) {
        int ig = ti*64 + ty*4 + i;
#pragma unroll
        for (int j = 0; j < 4; j++) {
            int jg = tj*64 + tx*4 + j;
            if (jg > ig) {
                float d2 = g_sq[gbase+ig] + g_sq[gbase+jg] - 2.f*acc[i][j];
                d2 = fmaxf(d2, 0.f);
                float dist = sqrtf(fmaxf(d2, 1e-12f));
                float pr = 1.f / (1.f + expf(dist - thr));
                int off = ig*(2*NN - 1 - ig)/2;
                int p = off + (jg - ig - 1);
                g_probs[(size_t)b*P_PAIR + p] = pr;
            }
        }
    }
}

// ---------------- per-graph top-K: radix select + bitonic sort ----------------
__global__ void __launch_bounds__(1024) topk_kernel(float* __restrict__ out) {
    __shared__ unsigned int hist[256];
    __shared__ unsigned int sh_prefix, sh_rem, sh_cnt;
    __shared__ unsigned long long buf[4096];

    int b = blockIdx.x;
    int t = threadIdx.x;
    const float* pp = g_probs + (size_t)b * P_PAIR;

    if (t == 0) { sh_prefix = 0u; sh_rem = K_SEL; sh_cnt = 0u; }
    __syncthreads();

    // 4-pass MSB radix select on prob bit patterns (positive floats: bits order == value order)
    for (int pass = 0; pass < 4; pass++) {
        int shift = 24 - pass*8;
        if (t < 256) hist[t] = 0u;
        __syncthreads();
        unsigned int prefix = sh_prefix;
        for (int p = t; p < P_PAIR; p += 1024) {
            unsigned int ob = __float_as_uint(pp[p]);
            bool match = (pass == 0) || ((ob >> (shift+8)) == (prefix >> (shift+8)));
            if (match) atomicAdd(&hist[(ob >> shift) & 0xFFu], 1u);
        }
        __syncthreads();
        if (t == 0) {
            unsigned int rem = sh_rem;
            int bin = 255;
            while (bin > 0 && rem > hist[bin]) { rem -= hist[bin]; bin--; }
            sh_rem = rem;
            sh_prefix = prefix | ((unsigned int)bin << shift);
        }
        __syncthreads();
    }
    unsigned int T = sh_prefix;

    // gather candidates >= T
    for (int p = t; p < P_PAIR; p += 1024) {
        unsigned int ob = __float_as_uint(pp[p]);
        if (ob >= T) {
            unsigned int pos = atomicAdd(&sh_cnt, 1u);
            if (pos < 4096u)
                buf[pos] = ((unsigned long long)ob << 32) |
                           (unsigned long long)(0xFFFFFFFFu - (unsigned int)p);
        }
    }
    __syncthreads();
    unsigned int cnt = sh_cnt; if (cnt > 4096u) cnt = 4096u;
    for (unsigned int i = cnt + t; i < 4096u; i += 1024u) buf[i] = 0ull;
    __syncthreads();

    // bitonic sort, descending (key = prob bits desc, then index asc via ~p)
    for (int k = 2; k <= 4096; k <<= 1) {
        for (int j = k >> 1; j > 0; j >>= 1) {
            for (int i = t; i < 4096; i += 1024) {
                int l = i ^ j;
                if (l > i) {
                    unsigned long long a = buf[i], c = buf[l];
                    bool up = ((i & k) != 0);        // up-block -> ascending
                    if ((!up && a < c) || (up && a > c)) { buf[i] = c; buf[l] = a; }
                }
            }
            __syncthreads();
        }
    }

    // emit top-K: probs, edge_index (u,v as floats)
    for (int k2 = t; k2 < K_SEL; k2 += 1024) {
        unsigned long long key = buf[k2];
        unsigned int ob = (unsigned int)(key >> 32);
        unsigned int p  = 0xFFFFFFFFu - (unsigned int)(key & 0xFFFFFFFFull);
        float prob = __uint_as_float(ob);
        // invert p -> (i,j), i<j, row-major upper-tri order
        double tw = 2.0*NN - 1.0;
        int i = (int)((tw - sqrt(tw*tw - 8.0*(double)p)) * 0.5);
        if (i < 0) i = 0; if (i > NN-2) i = NN-2;
        while (i > 0 && i*(2*NN-1-i)/2 > (int)p) i--;
        while ((i+1)*(2*NN-1-(i+1))/2 <= (int)p) i++;
        int off = i*(2*NN-1-i)/2;
        int j = (int)p - off + i + 1;
        float u = (float)(i + b*NN);
        float v = (float)(j + b*NN);
        int base0 = E0 + b*2*K_SEL;
        out[base0 + k2]                  = u;   // row0: [u..., v...]
        out[base0 + K_SEL + k2]          = v;
        out[base0 + ROWLEN + k2]         = v;   // row1: [v..., u...]
        out[base0 + ROWLEN + K_SEL + k2] = u;
        out[TPB + b*K_SEL + k2] = prob;
    }
}

// ---------------- batch vector ----------------
__global__ void batch_kernel(float* __restrict__ out) {
    int idx = blockIdx.x * 256 + threadIdx.x;
    if (idx < M_ROWS) out[BB + idx] = (float)(idx / NN);
}

// ---------------- launch ----------------
extern "C" void kernel_launch(void* const* d_in, const int* in_sizes, int n_in,
                              void* d_out, int out_size) {
    const float* z      = (const float*)d_in[0];
    const int*   labels = (const int*)  d_in[1];
    const float* emb    = (const float*)d_in[2];
    const float* W1     = (const float*)d_in[3];
    const float* b1     = (const float*)d_in[4];
    const float* W2     = (const float*)d_in[5];
    const float* b2     = (const float*)d_in[6];
    const float* We     = (const float*)d_in[7];
    const float* be     = (const float*)d_in[8];
    const float* thr    = (const float*)d_in[9];
    float* out = (float*)d_out;

    float *inp, *y1, *h;
    cudaGetSymbolAddress((void**)&inp, g_inp);
    cudaGetSymbolAddress((void**)&y1,  g_y1);
    cudaGetSymbolAddress((void**)&h,   g_h);

    build_inp_kernel<<<M_ROWS, IN_D>>>(z, labels, emb);

    // y1 = relu(inp @ W1 + b1)
    gemm_bias_kernel<true ><<<dim3(HID_D/64,  M_ROWS/64), 256>>>(inp, W1, b1, y1, M_ROWS, IN_D, HID_D);
    // x = y1 @ W2 + b2  (written straight into d_out region 0)
    gemm_bias_kernel<false><<<dim3(FEAT_D/64, M_ROWS/64), 256>>>(y1, W2, b2, out, M_ROWS, HID_D, FEAT_D);
    // h = relu(x @ We + be)
    gemm_bias_kernel<true ><<<dim3(HID_D/64,  M_ROWS/64), 256>>>(out, We, be, h, M_ROWS, FEAT_D, HID_D);

    sq_kernel<<<M_ROWS/8, 256>>>();
    gram_probs_kernel<<<dim3(21, BG), 256>>>(thr);
    topk_kernel<<<BG, 1024>>>(out);
    batch_kernel<<<(M_ROWS + 255)/256, 256>>>(out);
}

// round 2
// speedup vs baseline: 1.4820x; 1.4820x over previous
#include <cuda_runtime.h>
#include <cstdint>

#define BG   64
#define NN   384
#define NOISE_D 128
#define CED_D   64
#define HID_D   512
#define FEAT_D  256
#define IN_D    192           // NOISE + CED
#define M_ROWS  (BG*NN)       // 24576
#define P_PAIR  73536         // N*(N-1)/2
#define K_SEL   3677          // round(0.05 * P)

// output layout (float32, concatenated reference tuple)
#define X_SIZE   (M_ROWS*FEAT_D)        // 6291456
#define E0       X_SIZE
#define ROWLEN   (BG*2*K_SEL)           // 470656
#define BB       (E0 + 2*ROWLEN)        // 7232768
#define TPB      (BB + M_ROWS)          // 7257344

// ---------------- scratch (device globals; no allocation) ----------------
__device__ float g_inp[M_ROWS*IN_D];
__device__ float g_y1[M_ROWS*HID_D];
__device__ float g_h[M_ROWS*HID_D];
__device__ float g_sq[M_ROWS];
__device__ float g_probs[BG*P_PAIR];

// ---------------- build concatenated input ----------------
__global__ void build_inp_kernel(const float* __restrict__ z,
                                 const int* __restrict__ labels,
                                 const float* __restrict__ emb) {
    int node = blockIdx.x;
    int t = threadIdx.x;   // 192
    int b = node / NN;
    float v;
    if (t < NOISE_D) v = z[node*NOISE_D + t];
    else             v = emb[labels[b]*CED_D + (t - NOISE_D)];
    g_inp[node*IN_D + t] = v;
}

// ================= 128x128x8 double-buffered SGEMM =================
// C = act(A@B + bias). A [M,K] rm, B [K,Nc] rm. M%128==0, Nc%128==0, K%8==0.
// 256 threads, 8x8 micro-tile via split fragments (conflict-free LDS.128).
template<bool RELU>
__global__ void __launch_bounds__(256) sgemm128(const float* __restrict__ A,
                                                const float* __restrict__ Bw,
                                                const float* __restrict__ bias,
                                                float* __restrict__ C,
                                                int M, int Kd, int Nc) {
    __shared__ float As[2][8][128];
    __shared__ float Bs[2][8][128];
    int tid = threadIdx.x;
    int m0 = blockIdx.y * 128, n0 = blockIdx.x * 128;

    int arow = tid >> 1,  acol = (tid & 1) * 4;   // A: 128 rows x 8k, float4
    int brow = tid >> 5,  bcol = (tid & 31) * 4;  // B: 8k x 128 cols, float4
    const float* Aptr = A + (size_t)(m0 + arow) * Kd + acol;
    const float* Bptr = Bw + (size_t)brow * Nc + n0 + bcol;

    int tr = (tid >> 4) * 4;   // row frag base (and +64)
    int tc = (tid & 15) * 4;   // col frag base (and +64)

    float acc[8][8];
#pragma unroll
    for (int i = 0; i < 8; i++)
#pragma unroll
        for (int j = 0; j < 8; j++) acc[i][j] = 0.f;

    // preload tile 0
    float4 av = *(const float4*)Aptr;
    float4 bv = *(const float4*)Bptr;
    As[0][acol+0][arow] = av.x; As[0][acol+1][arow] = av.y;
    As[0][acol+2][arow] = av.z; As[0][acol+3][arow] = av.w;
    *(float4*)&Bs[0][brow][bcol] = bv;
    __syncthreads();

    int nt = Kd >> 3;
    for (int t = 0; t < nt; t++) {
        int cur = t & 1, nxt = cur ^ 1;
        float4 a2, b2;
        if (t + 1 < nt) {
            a2 = *(const float4*)(Aptr + (t+1)*8);
            b2 = *(const float4*)(Bptr + (size_t)(t+1)*8*Nc);
        }
#pragma unroll
        for (int k = 0; k < 8; k++) {
            float af[8], bf[8];
            *(float4*)(af)   = *(const float4*)&As[cur][k][tr];
            *(float4*)(af+4) = *(const float4*)&As[cur][k][tr+64];
            *(float4*)(bf)   = *(const float4*)&Bs[cur][k][tc];
            *(float4*)(bf+4) = *(const float4*)&Bs[cur][k][tc+64];
#pragma unroll
            for (int i = 0; i < 8; i++)
#pragma unroll
                for (int j = 0; j < 8; j++) acc[i][j] += af[i]*bf[j];
        }
        if (t + 1 < nt) {
            As[nxt][acol+0][arow] = a2.x; As[nxt][acol+1][arow] = a2.y;
            As[nxt][acol+2][arow] = a2.z; As[nxt][acol+3][arow] = a2.w;
            *(float4*)&Bs[nxt][brow][bcol] = b2;
            __syncthreads();
        }
    }

    // epilogue: 2x2 blocks of 4x4, vectorized stores
    float4 bias0 = *(const float4*)(bias + n0 + tc);
    float4 bias1 = *(const float4*)(bias + n0 + tc + 64);
#pragma unroll
    for (int ih = 0; ih < 2; ih++) {
#pragma unroll
        for (int i = 0; i < 4; i++) {
            int m = m0 + tr + ih*64 + i;
            int ai = ih*4 + i;
            float4 v0, v1;
            v0.x = acc[ai][0] + bias0.x; v0.y = acc[ai][1] + bias0.y;
            v0.z = acc[ai][2] + bias0.z; v0.w = acc[ai][3] + bias0.w;
            v1.x = acc[ai][4] + bias1.x; v1.y = acc[ai][5] + bias1.y;
            v1.z = acc[ai][6] + bias1.z; v1.w = acc[ai][7] + bias1.w;
            if (RELU) {
                v0.x = fmaxf(v0.x,0.f); v0.y = fmaxf(v0.y,0.f);
                v0.z = fmaxf(v0.z,0.f); v0.w = fmaxf(v0.w,0.f);
                v1.x = fmaxf(v1.x,0.f); v1.y = fmaxf(v1.y,0.f);
                v1.z = fmaxf(v1.z,0.f); v1.w = fmaxf(v1.w,0.f);
            }
            *(float4*)(C + (size_t)m*Nc + n0 + tc)      = v0;
            *(float4*)(C + (size_t)m*Nc + n0 + tc + 64) = v1;
        }
    }
}

// ---------------- row sum of squares of h ----------------
__global__ void sq_kernel() {
    int row = blockIdx.x * 8 + (threadIdx.x >> 5);
    int lane = threadIdx.x & 31;
    const float* hp = g_h + (size_t)row * HID_D;
    float s = 0.f;
    for (int k = lane; k < HID_D; k += 32) { float v = hp[k]; s += v*v; }
#pragma unroll
    for (int o = 16; o > 0; o >>= 1) s += __shfl_down_sync(0xFFFFFFFFu, s, o);
    if (lane == 0) g_sq[row] = s;
}

// ======== gram (H H^T) -> dist -> sigmoid, 128x128 tiles, fused ========
// per-graph 3x3 tiles of 128; upper-tri tile pairs: 6 per graph.
__global__ void __launch_bounds__(256) gram_probs_kernel(const float* __restrict__ thr_p) {
    static const int TI[6] = {0,0,0,1,1,2};
    static const int TJ[6] = {0,1,2,1,2,2};
    int ti = TI[blockIdx.x], tj = TJ[blockIdx.x];
    int b = blockIdx.y;
    int gbase = b * NN;
    float thr = *thr_p;

    __shared__ float As[2][8][128];
    __shared__ float Bs[2][8][128];
    int tid = threadIdx.x;
    int lrow = tid >> 1, lcol = (tid & 1) * 4;
    const float* Aptr = g_h + (size_t)(gbase + ti*128 + lrow) * HID_D + lcol;
    const float* Bptr = g_h + (size_t)(gbase + tj*128 + lrow) * HID_D + lcol;

    int tr = (tid >> 4) * 4;
    int tc = (tid & 15) * 4;

    float acc[8][8];
#pragma unroll
    for (int i = 0; i < 8; i++)
#pragma unroll
        for (int j = 0; j < 8; j++) acc[i][j] = 0.f;

    float4 av = *(const float4*)Aptr;
    float4 bv = *(const float4*)Bptr;
    As[0][lcol+0][lrow] = av.x; As[0][lcol+1][lrow] = av.y;
    As[0][lcol+2][lrow] = av.z; As[0][lcol+3][lrow] = av.w;
    Bs[0][lcol+0][lrow] = bv.x; Bs[0][lcol+1][lrow] = bv.y;
    Bs[0][lcol+2][lrow] = bv.z; Bs[0][lcol+3][lrow] = bv.w;
    __syncthreads();

    const int nt = HID_D >> 3;
    for (int t = 0; t < nt; t++) {
        int cur = t & 1, nxt = cur ^ 1;
        float4 a2, b2;
        if (t + 1 < nt) {
            a2 = *(const float4*)(Aptr + (t+1)*8);
            b2 = *(const float4*)(Bptr + (t+1)*8);
        }
#pragma unroll
        for (int k = 0; k < 8; k++) {
            float af[8], bf[8];
            *(float4*)(af)   = *(const float4*)&As[cur][k][tr];
            *(float4*)(af+4) = *(const float4*)&As[cur][k][tr+64];
            *(float4*)(bf)   = *(const float4*)&Bs[cur][k][tc];
            *(float4*)(bf+4) = *(const float4*)&Bs[cur][k][tc+64];
#pragma unroll
            for (int i = 0; i < 8; i++)
#pragma unroll
                for (int j = 0; j < 8; j++) acc[i][j] += af[i]*bf[j];
        }
        if (t + 1 < nt) {
            As[nxt][lcol+0][lrow] = a2.x; As[nxt][lcol+1][lrow] = a2.y;
            As[nxt][lcol+2][lrow] = a2.z; As[nxt][lcol+3][lrow] = a2.w;
            Bs[nxt][lcol+0][lrow] = b2.x; Bs[nxt][lcol+1][lrow] = b2.y;
            Bs[nxt][lcol+2][lrow] = b2.z; Bs[nxt][lcol+3][lrow] = b2.w;
            __syncthreads();
        }
    }

    // epilogue: dist -> prob -> scatter to packed upper-tri index
#pragma unroll
    for (int ih = 0; ih < 2; ih++) {
#pragma unroll
        for (int i = 0; i < 4; i++) {
            int ig = ti*128 + tr + ih*64 + i;
            float sqi = g_sq[gbase + ig];
            int off = ig*(2*NN - 1 - ig)/2 - ig - 1;
#pragma unroll
            for (int jh = 0; jh < 2; jh++) {
#pragma unroll
                for (int j = 0; j < 4; j++) {
                    int jg = tj*128 + tc + jh*64 + j;
                    if (jg > ig) {
                        float d2 = sqi + g_sq[gbase + jg] - 2.f*acc[ih*4+i][jh*4+j];
                        float dist = sqrtf(fmaxf(fmaxf(d2, 0.f), 1e-12f));
                        float pr = 1.f / (1.f + expf(dist - thr));
                        g_probs[(size_t)b*P_PAIR + off + jg] = pr;
                    }
                }
            }
        }
    }
}

// ---------------- per-graph top-K: radix select + bitonic sort ----------------
__global__ void __launch_bounds__(1024) topk_kernel(float* __restrict__ out) {
    __shared__ unsigned int hist[256];
    __shared__ unsigned int sh_prefix, sh_rem, sh_cnt;
    __shared__ unsigned long long buf[4096];

    int b = blockIdx.x;
    int t = threadIdx.x;
    const float* pp = g_probs + (size_t)b * P_PAIR;

    if (t == 0) { sh_prefix = 0u; sh_rem = K_SEL; sh_cnt = 0u; }
    __syncthreads();

    for (int pass = 0; pass < 4; pass++) {
        int shift = 24 - pass*8;
        if (t < 256) hist[t] = 0u;
        __syncthreads();
        unsigned int prefix = sh_prefix;
        for (int p = t; p < P_PAIR; p += 1024) {
            unsigned int ob = __float_as_uint(pp[p]);
            bool match = (pass == 0) || ((ob >> (shift+8)) == (prefix >> (shift+8)));
            if (match) atomicAdd(&hist[(ob >> shift) & 0xFFu], 1u);
        }
        __syncthreads();
        if (t == 0) {
            unsigned int rem = sh_rem;
            int bin = 255;
            while (bin > 0 && rem > hist[bin]) { rem -= hist[bin]; bin--; }
            sh_rem = rem;
            sh_prefix = prefix | ((unsigned int)bin << shift);
        }
        __syncthreads();
    }
    unsigned int T = sh_prefix;

    for (int p = t; p < P_PAIR; p += 1024) {
        unsigned int ob = __float_as_uint(pp[p]);
        if (ob >= T) {
            unsigned int pos = atomicAdd(&sh_cnt, 1u);
            if (pos < 4096u)
                buf[pos] = ((unsigned long long)ob << 32) |
                           (unsigned long long)(0xFFFFFFFFu - (unsigned int)p);
        }
    }
    __syncthreads();
    unsigned int cnt = sh_cnt; if (cnt > 4096u) cnt = 4096u;
    for (unsigned int i = cnt + t; i < 4096u; i += 1024u) buf[i] = 0ull;
    __syncthreads();

    for (int k = 2; k <= 4096; k <<= 1) {
        for (int j = k >> 1; j > 0; j >>= 1) {
            for (int i = t; i < 4096; i += 1024) {
                int l = i ^ j;
                if (l > i) {
                    unsigned long long a = buf[i], c = buf[l];
                    bool up = ((i & k) != 0);
                    if ((!up && a < c) || (up && a > c)) { buf[i] = c; buf[l] = a; }
                }
            }
            __syncthreads();
        }
    }

    for (int k2 = t; k2 < K_SEL; k2 += 1024) {
        unsigned long long key = buf[k2];
        unsigned int ob = (unsigned int)(key >> 32);
        unsigned int p  = 0xFFFFFFFFu - (unsigned int)(key & 0xFFFFFFFFull);
        float prob = __uint_as_float(ob);
        double tw = 2.0*NN - 1.0;
        int i = (int)((tw - sqrt(tw*tw - 8.0*(double)p)) * 0.5);
        if (i < 0) i = 0; if (i > NN-2) i = NN-2;
        while (i > 0 && i*(2*NN-1-i)/2 > (int)p) i--;
        while ((i+1)*(2*NN-1-(i+1))/2 <= (int)p) i++;
        int off = i*(2*NN-1-i)/2;
        int j = (int)p - off + i + 1;
        float u = (float)(i + b*NN);
        float v = (float)(j + b*NN);
        int base0 = E0 + b*2*K_SEL;
        out[base0 + k2]                  = u;
        out[base0 + K_SEL + k2]          = v;
        out[base0 + ROWLEN + k2]         = v;
        out[base0 + ROWLEN + K_SEL + k2] = u;
        out[TPB + b*K_SEL + k2] = prob;
    }
}

// ---------------- batch vector ----------------
__global__ void batch_kernel(float* __restrict__ out) {
    int idx = blockIdx.x * 256 + threadIdx.x;
    if (idx < M_ROWS) out[BB + idx] = (float)(idx / NN);
}

// ---------------- launch ----------------
extern "C" void kernel_launch(void* const* d_in, const int* in_sizes, int n_in,
                              void* d_out, int out_size) {
    const float* z      = (const float*)d_in[0];
    const int*   labels = (const int*)  d_in[1];
    const float* emb    = (const float*)d_in[2];
    const float* W1     = (const float*)d_in[3];
    const float* b1     = (const float*)d_in[4];
    const float* W2     = (const float*)d_in[5];
    const float* b2     = (const float*)d_in[6];
    const float* We     = (const float*)d_in[7];
    const float* be     = (const float*)d_in[8];
    const float* thr    = (const float*)d_in[9];
    float* out = (float*)d_out;

    float *inp, *y1, *h;
    cudaGetSymbolAddress((void**)&inp, g_inp);
    cudaGetSymbolAddress((void**)&y1,  g_y1);
    cudaGetSymbolAddress((void**)&h,   g_h);

    build_inp_kernel<<<M_ROWS, IN_D>>>(z, labels, emb);

    // y1 = relu(inp @ W1 + b1)
    sgemm128<true ><<<dim3(HID_D/128,  M_ROWS/128), 256>>>(inp, W1, b1, y1, M_ROWS, IN_D, HID_D);
    // x = y1 @ W2 + b2  (written straight into d_out region 0)
    sgemm128<false><<<dim3(FEAT_D/128, M_ROWS/128), 256>>>(y1, W2, b2, out, M_ROWS, HID_D, FEAT_D);
    // h = relu(x @ We + be)
    sgemm128<true ><<<dim3(HID_D/128,  M_ROWS/128), 256>>>(out, We, be, h, M_ROWS, FEAT_D, HID_D);

    sq_kernel<<<M_ROWS/8, 256>>>();
    gram_probs_kernel<<<dim3(6, BG), 256>>>(thr);
    topk_kernel<<<BG, 1024>>>(out);
    batch_kernel<<<(M_ROWS + 255)/256, 256>>>(out);
}

// round 4
// speedup vs baseline: 1.5848x; 1.0694x over previous
#include <cuda_runtime.h>
#include <cstdint>

#define BG   64
#define NN   384
#define NOISE_D 128
#define CED_D   64
#define HID_D   512
#define FEAT_D  256
#define IN_D    192           // NOISE + CED
#define M_ROWS  (BG*NN)       // 24576
#define P_PAIR  73536         // N*(N-1)/2
#define K_SEL   3677          // round(0.05 * P)

// output layout (float32, concatenated reference tuple)
#define X_SIZE   (M_ROWS*FEAT_D)        // 6291456
#define E0       X_SIZE
#define ROWLEN   (BG*2*K_SEL)           // 470656
#define BB       (E0 + 2*ROWLEN)        // 7232768
#define TPB      (BB + M_ROWS)          // 7257344

// ---------------- scratch (device globals; no allocation) ----------------
__device__ float g_inp[M_ROWS*IN_D];
__device__ float g_y1[M_ROWS*HID_D];
__device__ float g_h[M_ROWS*HID_D];
__device__ float g_sq[M_ROWS];
__device__ float g_probs[BG*P_PAIR];

// ---------------- packed f32x2 helpers (Blackwell base ISA) ----------------
__device__ __forceinline__ unsigned long long dup2(float a) {
    unsigned long long r;
    unsigned int au = __float_as_uint(a);
    asm("mov.b64 %0, {%1, %1};" : "=l"(r) : "r"(au));
    return r;
}
__device__ __forceinline__ void fma2(unsigned long long& d, unsigned long long a,
                                     unsigned long long b) {
    asm("fma.rn.f32x2 %0, %1, %2, %0;" : "+l"(d) : "l"(a), "l"(b));
}
__device__ __forceinline__ void unpack2(unsigned long long v, float& lo, float& hi) {
    unsigned int l, h;
    asm("mov.b64 {%0, %1}, %2;" : "=r"(l), "=r"(h) : "l"(v));
    lo = __uint_as_float(l); hi = __uint_as_float(h);
}

// ---------------- build concatenated input ----------------
__global__ void build_inp_kernel(const float* __restrict__ z,
                                 const int* __restrict__ labels,
                                 const float* __restrict__ emb) {
    int node = blockIdx.x;
    int t = threadIdx.x;   // 192
    int b = node / NN;
    float v;
    if (t < NOISE_D) v = z[node*NOISE_D + t];
    else             v = emb[labels[b]*CED_D + (t - NOISE_D)];
    g_inp[node*IN_D + t] = v;
}

// ================= 128x128x8 double-buffered SGEMM (FFMA2) =================
// C = act(A@B + bias). A [M,K] rm, B [K,Nc] rm. M%128==0, Nc%128==0, K%8==0.
// 256 threads, 8x8 micro-tile; inner product via packed f32x2 FMA.
template<bool RELU>
__global__ void __launch_bounds__(256) sgemm128(const float* __restrict__ A,
                                                const float* __restrict__ Bw,
                                                const float* __restrict__ bias,
                                                float* __restrict__ C,
                                                int M, int Kd, int Nc) {
    __shared__ float As[2][8][128];
    __shared__ float Bs[2][8][128];
    int tid = threadIdx.x;
    int m0 = blockIdx.y * 128, n0 = blockIdx.x * 128;

    int arow = tid >> 1,  acol = (tid & 1) * 4;   // A: 128 rows x 8k, float4
    int brow = tid >> 5,  bcol = (tid & 31) * 4;  // B: 8k x 128 cols, float4
    const float* Aptr = A + (size_t)(m0 + arow) * Kd + acol;
    const float* Bptr = Bw + (size_t)brow * Nc + n0 + bcol;

    int tr = (tid >> 4) * 4;   // row frag base (and +64)
    int tc = (tid & 15) * 4;   // col frag base (and +64)

    unsigned long long acc2[8][4];
#pragma unroll
    for (int i = 0; i < 8; i++)
#pragma unroll
        for (int j = 0; j < 4; j++) acc2[i][j] = 0ull;

    // preload tile 0
    float4 av = *(const float4*)Aptr;
    float4 bv = *(const float4*)Bptr;
    As[0][acol+0][arow] = av.x; As[0][acol+1][arow] = av.y;
    As[0][acol+2][arow] = av.z; As[0][acol+3][arow] = av.w;
    *(float4*)&Bs[0][brow][bcol] = bv;
    __syncthreads();

    int nt = Kd >> 3;
    for (int t = 0; t < nt; t++) {
        int cur = t & 1, nxt = cur ^ 1;
        float4 a2, b2;
        if (t + 1 < nt) {
            a2 = *(const float4*)(Aptr + (t+1)*8);
            b2 = *(const float4*)(Bptr + (size_t)(t+1)*8*Nc);
        }
#pragma unroll
        for (int k = 0; k < 8; k++) {
            float af[8];
            unsigned long long bp[4];
            *(float4*)(af)   = *(const float4*)&As[cur][k][tr];
            *(float4*)(af+4) = *(const float4*)&As[cur][k][tr+64];
            ulonglong2 u0 = *(const ulonglong2*)&Bs[cur][k][tc];
            ulonglong2 u1 = *(const ulonglong2*)&Bs[cur][k][tc+64];
            bp[0] = u0.x; bp[1] = u0.y; bp[2] = u1.x; bp[3] = u1.y;
#pragma unroll
            for (int i = 0; i < 8; i++) {
                unsigned long long ad = dup2(af[i]);
#pragma unroll
                for (int j = 0; j < 4; j++) fma2(acc2[i][j], ad, bp[j]);
            }
        }
        if (t + 1 < nt) {
            As[nxt][acol+0][arow] = a2.x; As[nxt][acol+1][arow] = a2.y;
            As[nxt][acol+2][arow] = a2.z; As[nxt][acol+3][arow] = a2.w;
            *(float4*)&Bs[nxt][brow][bcol] = b2;
            __syncthreads();
        }
    }

    // epilogue: unpack, bias, relu, vectorized stores
    float4 bias0 = *(const float4*)(bias + n0 + tc);
    float4 bias1 = *(const float4*)(bias + n0 + tc + 64);
#pragma unroll
    for (int ih = 0; ih < 2; ih++) {
#pragma unroll
        for (int i = 0; i < 4; i++) {
            int m = m0 + tr + ih*64 + i;
            int ai = ih*4 + i;
            float4 v0, v1;
            unpack2(acc2[ai][0], v0.x, v0.y);
            unpack2(acc2[ai][1], v0.z, v0.w);
            unpack2(acc2[ai][2], v1.x, v1.y);
            unpack2(acc2[ai][3], v1.z, v1.w);
            v0.x += bias0.x; v0.y += bias0.y; v0.z += bias0.z; v0.w += bias0.w;
            v1.x += bias1.x; v1.y += bias1.y; v1.z += bias1.z; v1.w += bias1.w;
            if (RELU) {
                v0.x = fmaxf(v0.x,0.f); v0.y = fmaxf(v0.y,0.f);
                v0.z = fmaxf(v0.z,0.f); v0.w = fmaxf(v0.w,0.f);
                v1.x = fmaxf(v1.x,0.f); v1.y = fmaxf(v1.y,0.f);
                v1.z = fmaxf(v1.z,0.f); v1.w = fmaxf(v1.w,0.f);
            }
            *(float4*)(C + (size_t)m*Nc + n0 + tc)      = v0;
            *(float4*)(C + (size_t)m*Nc + n0 + tc + 64) = v1;
        }
    }
}

// ---------------- row sum of squares of h ----------------
__global__ void sq_kernel() {
    int row = blockIdx.x * 8 + (threadIdx.x >> 5);
    int lane = threadIdx.x & 31;
    const float* hp = g_h + (size_t)row * HID_D;
    float s = 0.f;
    for (int k = lane; k < HID_D; k += 32) { float v = hp[k]; s += v*v; }
#pragma unroll
    for (int o = 16; o > 0; o >>= 1) s += __shfl_down_sync(0xFFFFFFFFu, s, o);
    if (lane == 0) g_sq[row] = s;
}

// ======== gram (H H^T) -> dist -> sigmoid, 128x128 tiles, fused, FFMA2 ========
__global__ void __launch_bounds__(256) gram_probs_kernel(const float* __restrict__ thr_p) {
    static const int TI[6] = {0,0,0,1,1,2};
    static const int TJ[6] = {0,1,2,1,2,2};
    int ti = TI[blockIdx.x], tj = TJ[blockIdx.x];
    int b = blockIdx.y;
    int gbase = b * NN;
    float thr = *thr_p;

    __shared__ float As[2][8][128];
    __shared__ float Bs[2][8][128];
    int tid = threadIdx.x;
    int lrow = tid >> 1, lcol = (tid & 1) * 4;
    const float* Aptr = g_h + (size_t)(gbase + ti*128 + lrow) * HID_D + lcol;
    const float* Bptr = g_h + (size_t)(gbase + tj*128 + lrow) * HID_D + lcol;

    int tr = (tid >> 4) * 4;
    int tc = (tid & 15) * 4;

    unsigned long long acc2[8][4];
#pragma unroll
    for (int i = 0; i < 8; i++)
#pragma unroll
        for (int j = 0; j < 4; j++) acc2[i][j] = 0ull;

    float4 av = *(const float4*)Aptr;
    float4 bv = *(const float4*)Bptr;
    As[0][lcol+0][lrow] = av.x; As[0][lcol+1][lrow] = av.y;
    As[0][lcol+2][lrow] = av.z; As[0][lcol+3][lrow] = av.w;
    Bs[0][lcol+0][lrow] = bv.x; Bs[0][lcol+1][lrow] = bv.y;
    Bs[0][lcol+2][lrow] = bv.z; Bs[0][lcol+3][lrow] = bv.w;
    __syncthreads();

    const int nt = HID_D >> 3;
    for (int t = 0; t < nt; t++) {
        int cur = t & 1, nxt = cur ^ 1;
        float4 a2, b2;
        if (t + 1 < nt) {
            a2 = *(const float4*)(Aptr + (t+1)*8);
            b2 = *(const float4*)(Bptr + (t+1)*8);
        }
#pragma unroll
        for (int k = 0; k < 8; k++) {
            float af[8];
            unsigned long long bp[4];
            *(float4*)(af)   = *(const float4*)&As[cur][k][tr];
            *(float4*)(af+4) = *(const float4*)&As[cur][k][tr+64];
            ulonglong2 u0 = *(const ulonglong2*)&Bs[cur][k][tc];
            ulonglong2 u1 = *(const ulonglong2*)&Bs[cur][k][tc+64];
            bp[0] = u0.x; bp[1] = u0.y; bp[2] = u1.x; bp[3] = u1.y;
#pragma unroll
            for (int i = 0; i < 8; i++) {
                unsigned long long ad = dup2(af[i]);
#pragma unroll
                for (int j = 0; j < 4; j++) fma2(acc2[i][j], ad, bp[j]);
            }
        }
        if (t + 1 < nt) {
            As[nxt][lcol+0][lrow] = a2.x; As[nxt][lcol+1][lrow] = a2.y;
            As[nxt][lcol+2][lrow] = a2.z; As[nxt][lcol+3][lrow] = a2.w;
            Bs[nxt][lcol+0][lrow] = b2.x; Bs[nxt][lcol+1][lrow] = b2.y;
            Bs[nxt][lcol+2][lrow] = b2.z; Bs[nxt][lcol+3][lrow] = b2.w;
            __syncthreads();
        }
    }

    // epilogue: dist -> prob -> scatter to packed upper-tri index
#pragma unroll
    for (int ih = 0; ih < 2; ih++) {
#pragma unroll
        for (int i = 0; i < 4; i++) {
            int ig = ti*128 + tr + ih*64 + i;
            int ai = ih*4 + i;
            float sqi = g_sq[gbase + ig];
            int off = ig*(2*NN - 1 - ig)/2 - ig - 1;
            float g[8];
            unpack2(acc2[ai][0], g[0], g[1]);
            unpack2(acc2[ai][1], g[2], g[3]);
            unpack2(acc2[ai][2], g[4], g[5]);
            unpack2(acc2[ai][3], g[6], g[7]);
#pragma unroll
            for (int jh = 0; jh < 2; jh++) {
#pragma unroll
                for (int j = 0; j < 4; j++) {
                    int jg = tj*128 + tc + jh*64 + j;
                    if (jg > ig) {
                        float d2 = sqi + g_sq[gbase + jg] - 2.f*g[jh*4+j];
                        float dist = sqrtf(fmaxf(fmaxf(d2, 0.f), 1e-12f));
                        float pr = 1.f / (1.f + expf(dist - thr));
                        g_probs[(size_t)b*P_PAIR + off + jg] = pr;
                    }
                }
            }
        }
    }
}

// ---------------- per-graph top-K: radix select + bitonic sort ----------------
__global__ void __launch_bounds__(1024) topk_kernel(float* __restrict__ out) {
    __shared__ unsigned int hist[256];
    __shared__ unsigned int sh_prefix, sh_rem, sh_cnt;
    __shared__ unsigned long long buf[4096];

    int b = blockIdx.x;
    int t = threadIdx.x;
    const float* pp = g_probs + (size_t)b * P_PAIR;

    if (t == 0) { sh_prefix = 0u; sh_rem = K_SEL; sh_cnt = 0u; }
    __syncthreads();

    for (int pass = 0; pass < 4; pass++) {
        int shift = 24 - pass*8;
        if (t < 256) hist[t] = 0u;
        __syncthreads();
        unsigned int prefix = sh_prefix;
        for (int p = t; p < P_PAIR; p += 1024) {
            unsigned int ob = __float_as_uint(pp[p]);
            bool match = (pass == 0) || ((ob >> (shift+8)) == (prefix >> (shift+8)));
            if (match) atomicAdd(&hist[(ob >> shift) & 0xFFu], 1u);
        }
        __syncthreads();
        if (t == 0) {
            unsigned int rem = sh_rem;
            int bin = 255;
            while (bin > 0 && rem > hist[bin]) { rem -= hist[bin]; bin--; }
            sh_rem = rem;
            sh_prefix = prefix | ((unsigned int)bin << shift);
        }
        __syncthreads();
    }
    unsigned int T = sh_prefix;

    for (int p = t; p < P_PAIR; p += 1024) {
        unsigned int ob = __float_as_uint(pp[p]);
        if (ob >= T) {
            unsigned int pos = atomicAdd(&sh_cnt, 1u);
            if (pos < 4096u)
                buf[pos] = ((unsigned long long)ob << 32) |
                           (unsigned long long)(0xFFFFFFFFu - (unsigned int)p);
        }
    }
    __syncthreads();
    unsigned int cnt = sh_cnt; if (cnt > 4096u) cnt = 4096u;
    for (unsigned int i = cnt + t; i < 4096u; i += 1024u) buf[i] = 0ull;
    __syncthreads();

    for (int k = 2; k <= 4096; k <<= 1) {
        for (int j = k >> 1; j > 0; j >>= 1) {
            for (int i = t; i < 4096; i += 1024) {
                int l = i ^ j;
                if (l > i) {
                    unsigned long long a = buf[i], c = buf[l];
                    bool up = ((i & k) != 0);
                    if ((!up && a < c) || (up && a > c)) { buf[i] = c; buf[l] = a; }
                }
            }
            __syncthreads();
        }
    }

    for (int k2 = t; k2 < K_SEL; k2 += 1024) {
        unsigned long long key = buf[k2];
        unsigned int ob = (unsigned int)(key >> 32);
        unsigned int p  = 0xFFFFFFFFu - (unsigned int)(key & 0xFFFFFFFFull);
        float prob = __uint_as_float(ob);
        double tw = 2.0*NN - 1.0;
        int i = (int)((tw - sqrt(tw*tw - 8.0*(double)p)) * 0.5);
        if (i < 0) i = 0; if (i > NN-2) i = NN-2;
        while (i > 0 && i*(2*NN-1-i)/2 > (int)p) i--;
        while ((i+1)*(2*NN-1-(i+1))/2 <= (int)p) i++;
        int off = i*(2*NN-1-i)/2;
        int j = (int)p - off + i + 1;
        float u = (float)(i + b*NN);
        float v = (float)(j + b*NN);
        int base0 = E0 + b*2*K_SEL;
        out[base0 + k2]                  = u;
        out[base0 + K_SEL + k2]          = v;
        out[base0 + ROWLEN + k2]         = v;
        out[base0 + ROWLEN + K_SEL + k2] = u;
        out[TPB + b*K_SEL + k2] = prob;
    }
}

// ---------------- batch vector ----------------
__global__ void batch_kernel(float* __restrict__ out) {
    int idx = blockIdx.x * 256 + threadIdx.x;
    if (idx < M_ROWS) out[BB + idx] = (float)(idx / NN);
}

// ---------------- launch ----------------
extern "C" void kernel_launch(void* const* d_in, const int* in_sizes, int n_in,
                              void* d_out, int out_size) {
    const float* z      = (const float*)d_in[0];
    const int*   labels = (const int*)  d_in[1];
    const float* emb    = (const float*)d_in[2];
    const float* W1     = (const float*)d_in[3];
    const float* b1     = (const float*)d_in[4];
    const float* W2     = (const float*)d_in[5];
    const float* b2     = (const float*)d_in[6];
    const float* We     = (const float*)d_in[7];
    const float* be     = (const float*)d_in[8];
    const float* thr    = (const float*)d_in[9];
    float* out = (float*)d_out;

    float *inp, *y1, *h;
    cudaGetSymbolAddress((void**)&inp, g_inp);
    cudaGetSymbolAddress((void**)&y1,  g_y1);
    cudaGetSymbolAddress((void**)&h,   g_h);

    build_inp_kernel<<<M_ROWS, IN_D>>>(z, labels, emb);

    // y1 = relu(inp @ W1 + b1)
    sgemm128<true ><<<dim3(HID_D/128,  M_ROWS/128), 256>>>(inp, W1, b1, y1, M_ROWS, IN_D, HID_D);
    // x = y1 @ W2 + b2  (written straight into d_out region 0)
    sgemm128<false><<<dim3(FEAT_D/128, M_ROWS/128), 256>>>(y1, W2, b2, out, M_ROWS, HID_D, FEAT_D);
    // h = relu(x @ We + be)
    sgemm128<true ><<<dim3(HID_D/128,  M_ROWS/128), 256>>>(out, We, be, h, M_ROWS, FEAT_D, HID_D);

    sq_kernel<<<M_ROWS/8, 256>>>();
    gram_probs_kernel<<<dim3(6, BG), 256>>>(thr);
    topk_kernel<<<BG, 1024>>>(out);
    batch_kernel<<<(M_ROWS + 255)/256, 256>>>(out);
}